// round 10
// baseline (speedup 1.0000x reference)
#include <cuda_runtime.h>

// Problem: B=4, C=256, D=H=W=16 -> N=4096, Cr=32
#define BB 4
#define CC 256
#define NN 4096
#define CRR 32
#define SCALE 0.17677669529663687f   // 32^-0.5
#define EPS 1e-5f

// The ONLY device global: U = wp @ wv (256 KB). q and k are recomputed
// per-CTA inside flash (no multi-MB scratch; previous rounds showed a fixed
// 128MiB device-memory materialization whenever multi-MB globals existed).
// No static initializers, no local (stack) arrays anywhere.
__device__ __align__(16) float g_U[CC * CC];   // [o][c]

// ---------------------------------------------------------------------------
// convU: U[o][c] = sum_m wp[o][m] * wv[m][c].  grid 16 x 256 threads.
// ---------------------------------------------------------------------------
__global__ void convU_kernel(const float* __restrict__ wp,
                             const float* __restrict__ wv) {
    __shared__ float wp_sm[16 * CC];   // 16KB
    const int og = blockIdx.x * 16;
    const int c = threadIdx.x;
    for (int idx = threadIdx.x; idx < 16 * CC; idx += 256)
        wp_sm[idx] = wp[og * CC + idx];
    __syncthreads();

    float acc[16];
    #pragma unroll
    for (int o = 0; o < 16; o++) acc[o] = 0.0f;
    for (int m = 0; m < CC; m++) {
        float wvv = wv[m * CC + c];      // coalesced
        #pragma unroll
        for (int o = 0; o < 16; o++) acc[o] += wp_sm[o * CC + m] * wvv;
    }
    #pragma unroll
    for (int o = 0; o < 16; o++) g_U[(og + o) * CC + c] = acc[o];
}

// ---------------------------------------------------------------------------
// Flash attention, fully self-contained:
//   q tile (64x32) computed per CTA from x1 and wq (prologue)
//   k tile (32x64) recomputed per j-tile from wk and the x2 tile in smem
//   z[i][c] = sum_j softmax_j(q_i.k_j*scale) * x2[c][j]
//   P[b][o][i-tile] = U @ z  -> written straight to d_out
// grid (N/64, B), 256 threads, dynamic smem 109,568 B (2 CTAs/SM).
// smem floats: vs[64][260] | qsT[32][68] | ksT[32][68] | ps[64][68]
//              | redm[64][16] | redl[64][16]  = 27,392 floats
// ---------------------------------------------------------------------------
__global__ void __launch_bounds__(256) flash_kernel(
    const float* __restrict__ x1, const float* __restrict__ x2,
    const float* __restrict__ wq, const float* __restrict__ wk,
    float* __restrict__ Pout) {
    extern __shared__ float sm[];
    float* vs   = sm;              // [64][260]  x2 tile (later: z tile)
    float* qsT  = sm + 16640;      // [32][68]   q transposed [o][i]
    float* ksT  = sm + 18816;      // [32][68]   k transposed [o][j]
    float* ps   = sm + 20992;      // [64][68]   p transposed [j][i]
    float* redm = sm + 25344;      // [64][16]
    float* redl = sm + 26368;      // [64][16]

    const int b = blockIdx.y;
    const int i0 = blockIdx.x * 64;
    const int tid = threadIdx.x;
    const int rg = tid & 15, cg = tid >> 4;   // S/PV tiling: i=rg*4+r, c=cg*16+k
    const int ko = tid >> 3, kj = tid & 7;    // q/k compute: o=ko, j/i = kj+8v

    // ---- Prologue: q[o][i] = sum_c wq[o][c] x1[b][c][i0+i] -> qsT ----
    {
        float qa[8];
        #pragma unroll
        for (int v = 0; v < 8; v++) qa[v] = 0.0f;
        for (int c0 = 0; c0 < CC; c0 += 64) {
            __syncthreads();
            // stage x1 chunk [64 c][64 i] into vs (row pitch 68)
            for (int idx = tid; idx < 1024; idx += 256) {
                int cr = idx >> 4, i4 = (idx & 15) * 4;
                float4 t = *(const float4*)(x1 + ((size_t)(b * CC + c0 + cr)) * NN + i0 + i4);
                *(float4*)(vs + cr * 68 + i4) = t;
            }
            __syncthreads();
            #pragma unroll 4
            for (int cr = 0; cr < 64; cr++) {
                float wqv = __ldg(wq + ko * CC + c0 + cr);
                #pragma unroll
                for (int v = 0; v < 8; v++)
                    qa[v] += wqv * vs[cr * 68 + kj + 8 * v];
            }
        }
        #pragma unroll
        for (int v = 0; v < 8; v++) qsT[ko * 68 + kj + 8 * v] = qa[v];
    }

    float acc[4][16];
    #pragma unroll
    for (int r = 0; r < 4; r++)
        #pragma unroll
        for (int k = 0; k < 16; k++) acc[r][k] = 0.0f;
    float m[4], l[4];
    #pragma unroll
    for (int r = 0; r < 4; r++) { m[r] = -1e30f; l[r] = 0.0f; }

    for (int jt = 0; jt < 64; jt++) {
        const int j0 = jt * 64;
        __syncthreads();   // prev iter's PV reads of vs / S reads of ksT done
        // x2 tile transposed into vs[j][c] (row pitch 260)
        for (int idx = tid; idx < 4096; idx += 256) {
            int c = idx >> 4, j4 = (idx & 15) * 4;
            float4 v = *(const float4*)(x2 + ((size_t)(b * CC + c)) * NN + j0 + j4);
            vs[(j4 + 0) * 260 + c] = v.x;
            vs[(j4 + 1) * 260 + c] = v.y;
            vs[(j4 + 2) * 260 + c] = v.z;
            vs[(j4 + 3) * 260 + c] = v.w;
        }
        __syncthreads();

        // k tile recompute: k[o][j] = sum_c wk[o][c] * x2tile[j][c]
        {
            float ka[8];
            #pragma unroll
            for (int v = 0; v < 8; v++) ka[v] = 0.0f;
            #pragma unroll 4
            for (int c4 = 0; c4 < 64; c4++) {
                float4 w4 = __ldg((const float4*)(wk + ko * CC + c4 * 4));
                #pragma unroll
                for (int v = 0; v < 8; v++) {
                    float4 xv = *(float4*)(vs + (kj + 8 * v) * 260 + c4 * 4);
                    ka[v] += w4.x * xv.x + w4.y * xv.y + w4.z * xv.z + w4.w * xv.w;
                }
            }
            #pragma unroll
            for (int v = 0; v < 8; v++) ksT[ko * 68 + kj + 8 * v] = ka[v];
        }
        __syncthreads();

        // S tile: s[jj][r], i = i0+rg*4+r, j = j0+cg*4+jj
        float s[4][4];
        #pragma unroll
        for (int jj = 0; jj < 4; jj++)
            #pragma unroll
            for (int r = 0; r < 4; r++) s[jj][r] = 0.0f;
        #pragma unroll
        for (int kk = 0; kk < 32; kk++) {
            float4 qv = *(float4*)(qsT + kk * 68 + rg * 4);
            float4 kv = *(float4*)(ksT + kk * 68 + cg * 4);
            s[0][0] += kv.x*qv.x; s[0][1] += kv.x*qv.y; s[0][2] += kv.x*qv.z; s[0][3] += kv.x*qv.w;
            s[1][0] += kv.y*qv.x; s[1][1] += kv.y*qv.y; s[1][2] += kv.y*qv.z; s[1][3] += kv.y*qv.w;
            s[2][0] += kv.z*qv.x; s[2][1] += kv.z*qv.y; s[2][2] += kv.z*qv.z; s[2][3] += kv.z*qv.w;
            s[3][0] += kv.w*qv.x; s[3][1] += kv.w*qv.y; s[3][2] += kv.w*qv.z; s[3][3] += kv.w*qv.w;
        }
        #pragma unroll
        for (int jj = 0; jj < 4; jj++)
            #pragma unroll
            for (int r = 0; r < 4; r++) s[jj][r] *= SCALE;

        // row max
        #pragma unroll
        for (int r = 0; r < 4; r++) {
            float pm = fmaxf(fmaxf(s[0][r], s[1][r]), fmaxf(s[2][r], s[3][r]));
            redm[(rg * 4 + r) * 16 + cg] = pm;
        }
        __syncthreads();

        float mnew[4], fsc[4];
        #pragma unroll
        for (int r = 0; r < 4; r++) {
            float mm = m[r];
            const float* rr = redm + (rg * 4 + r) * 16;
            #pragma unroll
            for (int g = 0; g < 16; g++) mm = fmaxf(mm, rr[g]);
            mnew[r] = mm;
            fsc[r] = __expf(m[r] - mm);
            m[r] = mm;
        }
        float pl[4] = {0.f, 0.f, 0.f, 0.f};
        #pragma unroll
        for (int jj = 0; jj < 4; jj++) {
            float p0 = __expf(s[jj][0] - mnew[0]);
            float p1 = __expf(s[jj][1] - mnew[1]);
            float p2 = __expf(s[jj][2] - mnew[2]);
            float p3 = __expf(s[jj][3] - mnew[3]);
            pl[0] += p0; pl[1] += p1; pl[2] += p2; pl[3] += p3;
            *(float4*)(ps + (cg * 4 + jj) * 68 + rg * 4) = make_float4(p0, p1, p2, p3);
        }
        #pragma unroll
        for (int r = 0; r < 4; r++) redl[(rg * 4 + r) * 16 + cg] = pl[r];
        __syncthreads();

        #pragma unroll
        for (int r = 0; r < 4; r++) {
            float ls = 0.0f;
            const float* rr = redl + (rg * 4 + r) * 16;
            #pragma unroll
            for (int g = 0; g < 16; g++) ls += rr[g];
            l[r] = l[r] * fsc[r] + ls;
            #pragma unroll
            for (int k = 0; k < 16; k++) acc[r][k] *= fsc[r];
        }

        // PV: acc[r][c] += p[i][j] * x2tile[j][c]
        #pragma unroll 4
        for (int j = 0; j < 64; j++) {
            float4 pv = *(float4*)(ps + j * 68 + rg * 4);
            #pragma unroll
            for (int k = 0; k < 4; k++) {
                float4 vv = *(float4*)(vs + j * 260 + cg * 16 + k * 4);
                acc[0][k*4+0] += pv.x * vv.x; acc[0][k*4+1] += pv.x * vv.y;
                acc[0][k*4+2] += pv.x * vv.z; acc[0][k*4+3] += pv.x * vv.w;
                acc[1][k*4+0] += pv.y * vv.x; acc[1][k*4+1] += pv.y * vv.y;
                acc[1][k*4+2] += pv.y * vv.z; acc[1][k*4+3] += pv.y * vv.w;
                acc[2][k*4+0] += pv.z * vv.x; acc[2][k*4+1] += pv.z * vv.y;
                acc[2][k*4+2] += pv.z * vv.z; acc[2][k*4+3] += pv.z * vv.w;
                acc[3][k*4+0] += pv.w * vv.x; acc[3][k*4+1] += pv.w * vv.y;
                acc[3][k*4+2] += pv.w * vv.z; acc[3][k*4+3] += pv.w * vv.w;
            }
        }
    }

    // ---- epilogue: z -> vs, then P = U @ z (U read from global, L2-hot) ----
    __syncthreads();
    #pragma unroll
    for (int r = 0; r < 4; r++) {
        float inv = 1.0f / l[r];
        #pragma unroll
        for (int k4 = 0; k4 < 4; k4++) {
            float4 v = make_float4(acc[r][k4*4+0] * inv, acc[r][k4*4+1] * inv,
                                   acc[r][k4*4+2] * inv, acc[r][k4*4+3] * inv);
            *(float4*)(vs + (rg * 4 + r) * 260 + cg * 16 + k4 * 4) = v;
        }
    }
    __syncthreads();

    // thread owns output row o = tid; 4 chunks of 16 i's (no local arrays)
    const float* urow = g_U + (size_t)tid * CC;
    #pragma unroll
    for (int ch = 0; ch < 4; ch++) {
        float pacc[16];
        #pragma unroll
        for (int ii = 0; ii < 16; ii++) pacc[ii] = 0.0f;
        for (int c0 = 0; c0 < CC; c0 += 4) {
            float4 u4 = __ldg((const float4*)(urow + c0));
            #pragma unroll
            for (int ii = 0; ii < 16; ii++) {
                float4 z4 = *(float4*)(vs + (ch * 16 + ii) * 260 + c0);  // broadcast
                pacc[ii] += u4.x*z4.x + u4.y*z4.y + u4.z*z4.z + u4.w*z4.w;
            }
        }
        float* pb = Pout + ((size_t)(b * CC + tid)) * NN + i0 + ch * 16;
        #pragma unroll
        for (int q4 = 0; q4 < 4; q4++) {
            *(float4*)(pb + q4 * 4) = make_float4(pacc[q4*4+0], pacc[q4*4+1],
                                                  pacc[q4*4+2], pacc[q4*4+3]);
        }
    }
}

// ---------------------------------------------------------------------------
// Instance norm + residual, IN PLACE on d_out (holds P):
// grid (C, B), 256 threads.
// ---------------------------------------------------------------------------
__global__ void norm_kernel(const float* __restrict__ x1, float* __restrict__ out) {
    const int b = blockIdx.y, o = blockIdx.x, tid = threadIdx.x;
    float* pb = out + ((size_t)(b * CC + o)) * NN;
    float4 v[4];
    float s = 0.0f, s2 = 0.0f;
    #pragma unroll
    for (int k = 0; k < 4; k++) {
        v[k] = *(const float4*)(pb + (k * 256 + tid) * 4);
        s  += v[k].x + v[k].y + v[k].z + v[k].w;
        s2 += v[k].x*v[k].x + v[k].y*v[k].y + v[k].z*v[k].z + v[k].w*v[k].w;
    }
    #pragma unroll
    for (int off = 16; off > 0; off >>= 1) {
        s  += __shfl_xor_sync(0xffffffffu, s, off);
        s2 += __shfl_xor_sync(0xffffffffu, s2, off);
    }
    __shared__ float sm1[8], sm2[8];
    if ((tid & 31) == 0) { sm1[tid >> 5] = s; sm2[tid >> 5] = s2; }
    __syncthreads();
    s = 0.0f; s2 = 0.0f;
    #pragma unroll
    for (int w = 0; w < 8; w++) { s += sm1[w]; s2 += sm2[w]; }
    const float mean = s * (1.0f / NN);
    const float var = s2 * (1.0f / NN) - mean * mean;
    const float rstd = rsqrtf(var + EPS);

    const float* xb = x1 + ((size_t)(b * CC + o)) * NN;
    #pragma unroll
    for (int k = 0; k < 4; k++) {
        float4 xv = *(const float4*)(xb + (k * 256 + tid) * 4);
        float4 r;
        r.x = (v[k].x - mean) * rstd + xv.x;
        r.y = (v[k].y - mean) * rstd + xv.y;
        r.z = (v[k].z - mean) * rstd + xv.z;
        r.w = (v[k].w - mean) * rstd + xv.w;
        *(float4*)(pb + (k * 256 + tid) * 4) = r;
    }
}

// ---------------------------------------------------------------------------
extern "C" void kernel_launch(void* const* d_in, const int* in_sizes, int n_in,
                              void* d_out, int out_size) {
    // Resolve inputs by element count (preserving relative order):
    // 4194304 -> x1 then x2 ; 8192 -> wq then wk ; 65536 -> wv then wp
    const float *x1 = nullptr, *x2 = nullptr, *wq = nullptr, *wk = nullptr,
                *wv = nullptr, *wp = nullptr;
    for (int i = 0; i < n_in; i++) {
        const float* p = (const float*)d_in[i];
        if (in_sizes[i] == BB * CC * NN) { if (!x1) x1 = p; else x2 = p; }
        else if (in_sizes[i] == CRR * CC) { if (!wq) wq = p; else wk = p; }
        else if (in_sizes[i] == CC * CC) { if (!wv) wv = p; else wp = p; }
    }
    float* out = (float*)d_out;

    const int flash_smem = 27392 * sizeof(float);   // 109,568 B
    cudaFuncSetAttribute(flash_kernel,
                         cudaFuncAttributeMaxDynamicSharedMemorySize, flash_smem);

    convU_kernel<<<16, 256>>>(wp, wv);
    flash_kernel<<<dim3(NN / 64, BB), 256, flash_smem>>>(x1, x2, wq, wk, out);
    norm_kernel<<<dim3(CC, BB), 256>>>(x1, out);
}